// round 8
// baseline (speedup 1.0000x reference)
#include <cuda_runtime.h>
#include <cuda_fp16.h>
#include <utility>
#include <cstddef>

using u64 = unsigned long long;

// ---------------------------------------------------------------------------
// packed f32x2 primitives (FFMA2 exists only via PTX fma.rn.f32x2)
// ---------------------------------------------------------------------------
__device__ __forceinline__ u64 pack2(float lo, float hi) {
    u64 r; asm("mov.b64 %0, {%1, %2};" : "=l"(r) : "f"(lo), "f"(hi)); return r;
}
__device__ __forceinline__ void unpack2(u64 v, float& lo, float& hi) {
    asm("mov.b64 {%0, %1}, %2;" : "=f"(lo), "=f"(hi) : "l"(v));
}
__device__ __forceinline__ void fma2(u64& d, u64 a, u64 b) {
    asm("fma.rn.f32x2 %0, %1, %2, %3;" : "=l"(d) : "l"(a), "l"(b), "l"(d));
}
__device__ __forceinline__ float hlo(unsigned v) {
    __half2 h = *reinterpret_cast<__half2*>(&v); return __low2float(h);
}
__device__ __forceinline__ float hhi(unsigned v) {
    __half2 h = *reinterpret_cast<__half2*>(&v); return __high2float(h);
}

// 8 packed FMAs covering 16 permuted blade positions.
// Position order: blades [1,2, 3,4, 5,6, 7,8, 9,10, 11,12, 13,14, 0,15]
// pair grades:     g1    g1   g2   g2   g2    g3     g3    (g0,g4)
#define DO8(acc, qa, qb, qc, qd, p0, p1, p2, p3)                         \
    do {                                                                 \
        fma2((acc)[0], (qa).x, (p0)); fma2((acc)[1], (qa).y, (p0));      \
        fma2((acc)[2], (qb).x, (p1)); fma2((acc)[3], (qb).y, (p1));      \
        fma2((acc)[4], (qc).x, (p1)); fma2((acc)[5], (qc).y, (p2));      \
        fma2((acc)[6], (qd).x, (p2)); fma2((acc)[7], (qd).y, (p3));      \
    } while (0)

// unpack 8 pairs (permuted positions) into blade-indexed scalars
#define UNPK(acc, arr)                                                   \
    do {                                                                 \
        unpack2((acc)[0], (arr)[1],  (arr)[2]);                          \
        unpack2((acc)[1], (arr)[3],  (arr)[4]);                          \
        unpack2((acc)[2], (arr)[5],  (arr)[6]);                          \
        unpack2((acc)[3], (arr)[7],  (arr)[8]);                          \
        unpack2((acc)[4], (arr)[9],  (arr)[10]);                         \
        unpack2((acc)[5], (arr)[11], (arr)[12]);                         \
        unpack2((acc)[6], (arr)[13], (arr)[14]);                         \
        unpack2((acc)[7], (arr)[0],  (arr)[15]);                         \
    } while (0)

// build the 4 u64 packs for one tensor from 5 grade weights (f0..f4 = g0..g4)
#define MK_PACKS(p0, p1, p2, p3, f0, f1, f2, f3, f4)                      \
    u64 p0 = pack2(f1, f1), p1 = pack2(f2, f2),                           \
        p2 = pack2(f3, f3), p3 = pack2(f0, f4)

// ---------------------------------------------------------------------------
// Compile-time Clifford algebra G(3,0,1) tables
// Blade order: 1,e0,e1,e2,e3,e01,e02,e03,e12,e13,e23,e012,e013,e023,e123,e0123
// ---------------------------------------------------------------------------
namespace ga {

constexpr int MASK[16]  = {0,1,2,4,8,3,5,9,6,10,12,7,11,13,14,15};

constexpr int mask_to_idx(int m) {
    int r = 0;
    for (int i = 0; i < 16; i++) if (MASK[i] == m) r = i;
    return r;
}
constexpr int swaps(int a, int b) {
    int s = 0;
    for (int q = 0; q < 4; q++)
        if ((b >> q) & 1)
            for (int p = q + 1; p < 4; p++)
                if ((a >> p) & 1) s++;
    return s;
}
constexpr float rsign(int a, int b) { return (swaps(a, b) & 1) ? -1.0f : 1.0f; }

struct Tab { float s[16][16]; int k[16][16]; };

constexpr Tab make_gp() {
    Tab t{};
    for (int i = 0; i < 16; i++)
        for (int j = 0; j < 16; j++) {
            int a = MASK[i], b = MASK[j];
            float sg = rsign(a, b);
            if (a & b & 1) sg = 0.0f;            // e0^2 = 0
            t.s[i][j] = sg;
            t.k[i][j] = mask_to_idx(a ^ b);
        }
    return t;
}
constexpr float dsign(int i) { return rsign(MASK[i], 15 ^ MASK[i]); }
constexpr Tab make_join() {
    Tab t{};
    for (int i = 0; i < 16; i++)
        for (int j = 0; j < 16; j++) {
            int ci = 15 ^ MASK[i], cj = 15 ^ MASK[j];
            if (ci & cj) { t.s[i][j] = 0.0f; t.k[i][j] = 0; }
            else {
                int m = ci | cj;
                int p = mask_to_idx(15 ^ m);
                t.s[i][j] = dsign(i) * dsign(j) * rsign(ci, cj) * dsign(p);
                t.k[i][j] = p;
            }
        }
    return t;
}
constexpr Tab GP = make_gp();
constexpr Tab JN = make_join();

} // namespace ga

// static-for sparse bilinears (all indices compile-time)
template<int I, int J>
__device__ __forceinline__ void gp_term(float* p, const float* a, const float* b) {
    constexpr float s = ga::GP.s[I][J];
    constexpr int   k = ga::GP.k[I][J];
    if constexpr (s != 0.0f) p[k] += s * a[I] * b[J];
}
template<int I, int... Js>
__device__ __forceinline__ void gp_row(float* p, const float* a, const float* b,
                                       std::integer_sequence<int, Js...>) {
    (gp_term<I, Js>(p, a, b), ...);
}
template<int... Is>
__device__ __forceinline__ void gp_mat(float* p, const float* a, const float* b,
                                       std::integer_sequence<int, Is...>) {
    (gp_row<Is>(p, a, b, std::make_integer_sequence<int, 16>{}), ...);
}
template<int I, int J>
__device__ __forceinline__ void jn_term(float* p, const float* a, const float* b) {
    constexpr float s = ga::JN.s[I][J];
    constexpr int   k = ga::JN.k[I][J];
    if constexpr (s != 0.0f) p[k] += s * a[I] * b[J];
}
template<int I, int... Js>
__device__ __forceinline__ void jn_row(float* p, const float* a, const float* b,
                                       std::integer_sequence<int, Js...>) {
    (jn_term<I, Js>(p, a, b), ...);
}
template<int... Is>
__device__ __forceinline__ void jn_mat(float* p, const float* a, const float* b,
                                       std::integer_sequence<int, Is...>) {
    (jn_row<Is>(p, a, b, std::make_integer_sequence<int, 16>{}), ...);
}

// ---------------------------------------------------------------------------
// Problem constants: B=32, N=1024, Cin=64, Cout=64, H=32 -> 32768 tokens
// ---------------------------------------------------------------------------
static constexpr int TOKENS   = 32 * 1024;
static constexpr int NPAIRS   = TOKENS / 2;         // 16384 token pairs
static constexpr int WARPS_PB = 12;
static constexpr int THREADS  = WARPS_PB * 32;      // 384
static constexpr int GRID     = 152;                // persistent, 1 CTA/SM

// fp16 weight tables (static __device__ -> no allocation)
// grade-plane layout [g][slot] where slot = i*32 + c (proj) / cc*32 + o (final)
// g_WPH_P[g*2048 + slot] = (prodX, prodY);  g_WPH_J = (joinX, joinY)
// g_WFH  [g*2048 + slot] = (w_final[o], w_final[o+32])
__device__ __align__(16) __half2 g_WPH_P[5 * 2048];
__device__ __align__(16) __half2 g_WPH_J[5 * 2048];
__device__ __align__(16) __half2 g_WFH  [5 * 2048];

__global__ void prep_kernel(const float* __restrict__ wpx, const float* __restrict__ wpy,
                            const float* __restrict__ wjx, const float* __restrict__ wjy,
                            const float* __restrict__ wf) {
    int idx = blockIdx.x * blockDim.x + threadIdx.x;     // over 2048 slots
    if (idx < 2048) {
        int c = idx & 31;            // lane channel (c for proj, o for final)
        int i = idx >> 5;            // reduction index (i for proj, cc for final)
        #pragma unroll
        for (int g = 0; g < 5; g++) {
            int src = (g * 32 + c) * 64 + i;             // proj weights [5][32][64]
            g_WPH_P[g * 2048 + idx] = __floats2half2_rn(wpx[src], wpy[src]);
            g_WPH_J[g * 2048 + idx] = __floats2half2_rn(wjx[src], wjy[src]);
            // final weights [5][64 o][64 cc]; here c = o, i = cc
            g_WFH[g * 2048 + idx] = __floats2half2_rn(wf[(g * 64 + c) * 64 + i],
                                                      wf[(g * 64 + c + 32) * 64 + i]);
        }
    }
}

// smem: tb 24 slots x 1024 floats = 96 KB; three weight tables 40 KB each
static constexpr int TB_FLOATS  = 24 * 1024;
static constexpr int WTAB_H2    = 5 * 2048;          // 10240 half2 per table
static constexpr int SMEM_BYTES = TB_FLOATS * 4 + 3 * WTAB_H2 * 4;  // 221184

// one projection pass: one (X,Y) weight table, 2 tokens
__device__ __forceinline__ void runA(const unsigned* __restrict__ Wbase, int lane,
                                     const ulonglong2* __restrict__ xv0,
                                     const ulonglong2* __restrict__ xv1,
                                     u64 aX0[8], u64 aY0[8], u64 aX1[8], u64 aY1[8]) {
    const unsigned* Wu = Wbase + lane;
    #pragma unroll 1
    for (int i = 0; i < 64; i++, Wu += 32) {
        unsigned w0 = Wu[0],        w1 = Wu[2048],     w2 = Wu[2 * 2048],
                 w3 = Wu[3 * 2048], w4 = Wu[4 * 2048];
        ulonglong2 a0 = xv0[i * 4 + 0], b0 = xv0[i * 4 + 1],
                   c0 = xv0[i * 4 + 2], d0 = xv0[i * 4 + 3];
        ulonglong2 a1 = xv1[i * 4 + 0], b1 = xv1[i * 4 + 1],
                   c1 = xv1[i * 4 + 2], d1 = xv1[i * 4 + 3];
        {   // tensor X = low halves
            MK_PACKS(p0, p1, p2, p3, hlo(w0), hlo(w1), hlo(w2), hlo(w3), hlo(w4));
            DO8(aX0, a0, b0, c0, d0, p0, p1, p2, p3);
            DO8(aX1, a1, b1, c1, d1, p0, p1, p2, p3);
        }
        {   // tensor Y = high halves
            MK_PACKS(p0, p1, p2, p3, hhi(w0), hhi(w1), hhi(w2), hhi(w3), hhi(w4));
            DO8(aY0, a0, b0, c0, d0, p0, p1, p2, p3);
            DO8(aY1, a1, b1, c1, d1, p0, p1, p2, p3);
        }
    }
}

__global__ __launch_bounds__(THREADS, 1)
void gbl_kernel(const float* __restrict__ x, const float* __restrict__ ref,
                float* __restrict__ out) {
    extern __shared__ float smem[];
    float*    tb   = smem;
    unsigned* WP_P = reinterpret_cast<unsigned*>(smem + TB_FLOATS);
    unsigned* WP_J = WP_P + WTAB_H2;
    unsigned* WFHs = WP_J + WTAB_H2;

    const int tid  = threadIdx.x;
    const int w    = tid >> 5;
    const int lane = tid & 31;
    const int q    = lane & 3;
    const int s0   = w * 2;

    // ---- stage the three weight tables once (no block barriers after) ----
    {
        uint4*       d = reinterpret_cast<uint4*>(WP_P);
        const uint4* a = reinterpret_cast<const uint4*>(g_WPH_P);
        const uint4* b = reinterpret_cast<const uint4*>(g_WPH_J);
        const uint4* c = reinterpret_cast<const uint4*>(g_WFH);
        constexpr int QT = WTAB_H2 / 4;     // 2560 uint4 per table
        for (int i = tid; i < QT; i += THREADS) {
            d[i] = a[i]; d[QT + i] = b[i]; d[2 * QT + i] = c[i];
        }
    }
    __syncthreads();

    // ---- barrier-free persistent loop: each warp owns its token pair ----
    for (int pair = blockIdx.x * WARPS_PB + w; pair < NPAIRS; pair += GRID * WARPS_PB) {
        const int tok0 = pair * 2;

        // stage 2 tokens, blade-permuted [1..14,0,15], into warp-private slots
        #pragma unroll
        for (int t = 0; t < 2; t++) {
            const float4* xg = reinterpret_cast<const float4*>(x + (size_t)(tok0 + t) * 1024);
            float4* dst = reinterpret_cast<float4*>(tb + (s0 + t) * 1024);
            #pragma unroll
            for (int rep = 0; rep < 8; rep++) {
                float4 v = xg[rep * 32 + lane];          // channel i = rep*8 + lane>>2, quad q
                float firstx = __shfl_sync(0xffffffffu, v.x, lane & ~3);
                float nextx  = __shfl_down_sync(0xffffffffu, v.x, 1);
                float4 o;
                if (q < 3) o = make_float4(v.y, v.z, v.w, nextx);
                else       o = make_float4(v.y, v.z, firstx, v.w);
                dst[rep * 32 + (lane >> 2) * 4 + q] = o;
            }
        }
        __syncwarp();

        const ulonglong2* xv0 = reinterpret_cast<const ulonglong2*>(tb + s0 * 1024);
        const ulonglong2* xv1 = reinterpret_cast<const ulonglong2*>(tb + (s0 + 1) * 1024);

        // ===== Phase A pass 1: prodX/prodY projection + geometric product =====
        float prod0[16], prod1[16];
        {
            u64 aX0[8] = {}, aY0[8] = {}, aX1[8] = {}, aY1[8] = {};
            runA(WP_P, lane, xv0, xv1, aX0, aY0, aX1, aY1);
            float px[16], py[16];
            UNPK(aX0, px); UNPK(aY0, py);
            #pragma unroll
            for (int k = 0; k < 16; k++) prod0[k] = 0.0f;
            gp_mat(prod0, px, py, std::make_integer_sequence<int, 16>{});
            UNPK(aX1, px); UNPK(aY1, py);
            #pragma unroll
            for (int k = 0; k < 16; k++) prod1[k] = 0.0f;
            gp_mat(prod1, px, py, std::make_integer_sequence<int, 16>{});
        }

        // ===== Phase A pass 2: joinX/joinY projection + join product =========
        float jn0[16], jn1[16];
        {
            u64 aX0[8] = {}, aY0[8] = {}, aX1[8] = {}, aY1[8] = {};
            runA(WP_J, lane, xv0, xv1, aX0, aY0, aX1, aY1);
            float r0 = __ldg(ref + (size_t)tok0 * 16 + 15);
            float r1 = __ldg(ref + (size_t)(tok0 + 1) * 16 + 15);
            float jx[16], jy[16];
            UNPK(aX0, jx); UNPK(aY0, jy);
            #pragma unroll
            for (int k = 0; k < 16; k++) { jx[k] *= r0; jn0[k] = 0.0f; }
            jn_mat(jn0, jx, jy, std::make_integer_sequence<int, 16>{});
            UNPK(aX1, jx); UNPK(aY1, jy);
            #pragma unroll
            for (int k = 0; k < 16; k++) { jx[k] *= r1; jn1[k] = 0.0f; }
            jn_mat(jn1, jx, jy, std::make_integer_sequence<int, 16>{});
        }

        // ---- feats overlay x slots: permuted positions + XOR-swizzled slots ----
        __syncwarp();
        #pragma unroll
        for (int t = 0; t < 2; t++) {
            const float* prod = (t == 0) ? prod0 : prod1;
            const float* jn   = (t == 0) ? jn0   : jn1;
            float4* fb = reinterpret_cast<float4*>(tb + (s0 + t) * 1024);
            int ccP = lane, ccJ = lane + 32;
            int swP = ccP & 3, swJ = ccJ & 3;
            fb[ccP * 4 + (0 ^ swP)] = make_float4(prod[1],  prod[2],  prod[3],  prod[4]);
            fb[ccP * 4 + (1 ^ swP)] = make_float4(prod[5],  prod[6],  prod[7],  prod[8]);
            fb[ccP * 4 + (2 ^ swP)] = make_float4(prod[9],  prod[10], prod[11], prod[12]);
            fb[ccP * 4 + (3 ^ swP)] = make_float4(prod[13], prod[14], prod[0],  prod[15]);
            fb[ccJ * 4 + (0 ^ swJ)] = make_float4(jn[1],  jn[2],  jn[3],  jn[4]);
            fb[ccJ * 4 + (1 ^ swJ)] = make_float4(jn[5],  jn[6],  jn[7],  jn[8]);
            fb[ccJ * 4 + (2 ^ swJ)] = make_float4(jn[9],  jn[10], jn[11], jn[12]);
            fb[ccJ * 4 + (3 ^ swJ)] = make_float4(jn[13], jn[14], jn[0],  jn[15]);
        }
        __syncwarp();

        // ================= Phase C: final projection ==========================
        u64 o0a[8] = {}, o0b[8] = {}, o1a[8] = {}, o1b[8] = {};
        {
            const unsigned* Vu = WFHs + lane;
            const ulonglong2* fb0 = reinterpret_cast<const ulonglong2*>(tb + s0 * 1024);
            const ulonglong2* fb1 = reinterpret_cast<const ulonglong2*>(tb + (s0 + 1) * 1024);
            #pragma unroll 1
            for (int cc = 0; cc < 64; cc++, Vu += 32) {
                unsigned v0 = Vu[0],        v1 = Vu[2048],     v2 = Vu[2 * 2048],
                         v3 = Vu[3 * 2048], v4 = Vu[4 * 2048];
                int sw = cc & 3;
                ulonglong2 f00 = fb0[cc * 4 + (0 ^ sw)], f01 = fb0[cc * 4 + (1 ^ sw)],
                           f02 = fb0[cc * 4 + (2 ^ sw)], f03 = fb0[cc * 4 + (3 ^ sw)];
                ulonglong2 f10 = fb1[cc * 4 + (0 ^ sw)], f11 = fb1[cc * 4 + (1 ^ sw)],
                           f12 = fb1[cc * 4 + (2 ^ sw)], f13 = fb1[cc * 4 + (3 ^ sw)];
                {   // output o = lane (low halves)
                    MK_PACKS(p0, p1, p2, p3, hlo(v0), hlo(v1), hlo(v2), hlo(v3), hlo(v4));
                    DO8(o0a, f00, f01, f02, f03, p0, p1, p2, p3);
                    DO8(o1a, f10, f11, f12, f13, p0, p1, p2, p3);
                }
                {   // output o+32 (high halves)
                    MK_PACKS(p0, p1, p2, p3, hhi(v0), hhi(v1), hhi(v2), hhi(v3), hhi(v4));
                    DO8(o0b, f00, f01, f02, f03, p0, p1, p2, p3);
                    DO8(o1b, f10, f11, f12, f13, p0, p1, p2, p3);
                }
            }
        }

        // ---- stores: natural blade order ----
        {
            float4* op0 = reinterpret_cast<float4*>(out + (size_t)tok0 * 1024);
            float4* op1 = reinterpret_cast<float4*>(out + (size_t)(tok0 + 1) * 1024);
            float v[16];
            UNPK(o0a, v);
            op0[lane * 4 + 0] = make_float4(v[0], v[1], v[2], v[3]);
            op0[lane * 4 + 1] = make_float4(v[4], v[5], v[6], v[7]);
            op0[lane * 4 + 2] = make_float4(v[8], v[9], v[10], v[11]);
            op0[lane * 4 + 3] = make_float4(v[12], v[13], v[14], v[15]);
            UNPK(o0b, v);
            op0[(lane + 32) * 4 + 0] = make_float4(v[0], v[1], v[2], v[3]);
            op0[(lane + 32) * 4 + 1] = make_float4(v[4], v[5], v[6], v[7]);
            op0[(lane + 32) * 4 + 2] = make_float4(v[8], v[9], v[10], v[11]);
            op0[(lane + 32) * 4 + 3] = make_float4(v[12], v[13], v[14], v[15]);
            UNPK(o1a, v);
            op1[lane * 4 + 0] = make_float4(v[0], v[1], v[2], v[3]);
            op1[lane * 4 + 1] = make_float4(v[4], v[5], v[6], v[7]);
            op1[lane * 4 + 2] = make_float4(v[8], v[9], v[10], v[11]);
            op1[lane * 4 + 3] = make_float4(v[12], v[13], v[14], v[15]);
            UNPK(o1b, v);
            op1[(lane + 32) * 4 + 0] = make_float4(v[0], v[1], v[2], v[3]);
            op1[(lane + 32) * 4 + 1] = make_float4(v[4], v[5], v[6], v[7]);
            op1[(lane + 32) * 4 + 2] = make_float4(v[8], v[9], v[10], v[11]);
            op1[(lane + 32) * 4 + 3] = make_float4(v[12], v[13], v[14], v[15]);
        }
        __syncwarp();   // feats reads done before next iteration's x overwrite
    }
}

// ---------------------------------------------------------------------------
extern "C" void kernel_launch(void* const* d_in, const int* in_sizes, int n_in,
                              void* d_out, int out_size) {
    const float* x   = (const float*)d_in[0];
    const float* ref = (const float*)d_in[1];
    const float* wpx = (const float*)d_in[2];
    const float* wpy = (const float*)d_in[3];
    const float* wjx = (const float*)d_in[4];
    const float* wjy = (const float*)d_in[5];
    const float* wf  = (const float*)d_in[6];
    float* out = (float*)d_out;

    prep_kernel<<<8, 256>>>(wpx, wpy, wjx, wjy, wf);

    cudaFuncSetAttribute(gbl_kernel, cudaFuncAttributeMaxDynamicSharedMemorySize, SMEM_BYTES);
    gbl_kernel<<<GRID, THREADS, SMEM_BYTES>>>(x, ref, out);
}